// round 8
// baseline (speedup 1.0000x reference)
#include <cuda_runtime.h>
#include <cuda_bf16.h>

// Chamfer distance via direct-insert uniform grid, ONE persistent kernel,
// ONE grid barrier. B=2, N=M=8192, C=3, coords ~U[0,1).
//
//   Phase A: insert every point into its cell (fixed capacity CAP slots,
//            overflow -> per-set list).
//   grid_sync (single software barrier, spin-poll)
//   Phase B: each thread answers its queries (fixed mapping), scanning the
//            27 clamped neighbor cells with all count-loads issued upfront
//            (high MLP) + the (normally empty) overflow list; accumulates
//            per-direction sums IN REGISTERS.
//   Done-counter: last CTA sums per-CTA partials in fixed order, writes the
//            scalar output, re-zeros counts/overflow (graph-replay invariant).
//
// Determinism: thread->query mapping fixed; per-thread and per-block sum
// order fixed; cross-CTA sum in CTA-id order; cell-slot permutation from
// atomics only feeds fminf (permutation-invariant) -> bitwise deterministic.

#define G        16
#define NC       (G * G * G)
#define CAP      16
#define OVF_CAP  256
#define B_MAX    4
#define NSETS_MAX (2 * B_MAX)
#define BLK      256
#define MAXGRID  1024

__device__ int    g_cnt [NSETS_MAX * NC];                 // static zero; restored each run
__device__ float4 g_cell[NSETS_MAX * NC * CAP];
__device__ int    g_ovf_cnt[NSETS_MAX];                   // static zero; restored
__device__ float4 g_ovf [NSETS_MAX * OVF_CAP];
__device__ float  g_p0[MAXGRID], g_p1[MAXGRID];

__device__ unsigned int g_bar_count = 0;
__device__ unsigned int g_bar_gen   = 0;
__device__ unsigned int g_done      = 0;

__device__ __forceinline__ void grid_sync() {
    __threadfence();
    __syncthreads();
    if (threadIdx.x == 0) {
        const unsigned int gen = *(volatile unsigned int*)&g_bar_gen;
        const unsigned int t   = atomicAdd(&g_bar_count, 1u);
        if (t == gridDim.x - 1) {
            g_bar_count = 0;
            __threadfence();
            atomicAdd(&g_bar_gen, 1u);
        } else {
            while (*(volatile unsigned int*)&g_bar_gen == gen) { }
        }
    }
    __syncthreads();
    __threadfence();   // acquire: invalidate L1 so peer writes are visible
}

__device__ __forceinline__ int cell_of(float v) {
    int c = (int)(v * (float)G);
    return min(max(c, 0), G - 1);
}

__device__ __forceinline__ float block_sum(float v, float* red) {
#pragma unroll
    for (int o = 16; o > 0; o >>= 1)
        v += __shfl_xor_sync(0xffffffffu, v, o);
    if ((threadIdx.x & 31) == 0) red[threadIdx.x >> 5] = v;
    __syncthreads();
    float s = 0.f;
    if (threadIdx.x == 0) {
#pragma unroll
        for (int w = 0; w < BLK / 32; ++w) s += red[w];
    }
    __syncthreads();
    return s;   // valid in thread 0 only
}

__global__ __launch_bounds__(BLK, 2)
void chamfer_onebar_kernel(const float* __restrict__ pos,
                           const float* __restrict__ xhat,
                           float* __restrict__ out, int out_size,
                           int N, int M, int B) {
    const int nsets = 2 * B;
    const int maxP  = (N > M) ? N : M;
    const int gtid  = blockIdx.x * BLK + threadIdx.x;
    const int T     = gridDim.x * BLK;

    __shared__ float redf[BLK / 32];
    __shared__ bool  amLast;

    // ---------------- Phase A: insert ----------------
    for (int j = gtid; j < nsets * maxP; j += T) {
        const int sid   = j / maxP;
        const int i     = j - sid * maxP;
        const int cloud = sid / B;
        const int b     = sid % B;
        const int n     = cloud ? M : N;
        if (i < n) {
            const float* P = cloud ? xhat : pos;
            const float* p = P + ((size_t)b * n + i) * 3;
            const float x = p[0], y = p[1], z = p[2];
            const int cell = (cell_of(z) * G + cell_of(y)) * G + cell_of(x);
            const int slot = atomicAdd(&g_cnt[sid * NC + cell], 1);
            const float4 v = make_float4(x, y, z, x * x + y * y + z * z);
            if (slot < CAP) {
                g_cell[(sid * NC + cell) * CAP + slot] = v;
            } else {
                const int o = atomicAdd(&g_ovf_cnt[sid], 1);
                if (o < OVF_CAP) g_ovf[sid * OVF_CAP + o] = v;
            }
        }
    }
    grid_sync();

    // ---------------- Phase B: query (register accumulation) ----------------
    const float h = 1.0f / (float)G;
    float accD0 = 0.f, accD1 = 0.f;

    for (int j = gtid; j < nsets * maxP; j += T) {
        const int yb  = j / maxP;
        const int i   = j - yb * maxP;
        const int dir = yb / B;
        const int b   = yb % B;
        const int nQ  = dir ? M : N;
        if (i >= nQ) continue;
        const int sid_t = (1 - dir) * B + b;     // target cloud = other cloud

        const float* qp = ((dir ? xhat : pos) + ((size_t)b * nQ + i) * 3);
        const float qx = qp[0], qy = qp[1], qz = qp[2];
        const float qn = qx * qx + qy * qy + qz * qz;
        const float m2x = -2.0f * qx, m2y = -2.0f * qy, m2z = -2.0f * qz;
        const int cx = cell_of(qx), cy = cell_of(qy), cz = cell_of(qz);

        const int*    __restrict__ cnt  = g_cnt  + sid_t * NC;
        const float4* __restrict__ cell = g_cell + (size_t)sid_t * NC * CAP;

        // 27 clamped neighbor cells; duplicates at borders are harmless for min.
        int cb[27], cc[27];
#pragma unroll
        for (int s = 0; s < 27; ++s) {
            const int z = min(max(cz + s / 9 - 1, 0), G - 1);
            const int y = min(max(cy + (s / 3) % 3 - 1, 0), G - 1);
            const int x = min(max(cx + s % 3 - 1, 0), G - 1);
            const int c = (z * G + y) * G + x;
            cb[s] = c * CAP;
            cc[s] = cnt[c];          // 27 independent loads, one latency wave
        }

        float minAcc = 3.4e38f;
#pragma unroll
        for (int s = 0; s < 27; ++s) {
            const int c = min(cc[s], CAP);
            for (int k = 0; k < c; ++k) {
                const float4 tt = cell[cb[s] + k];
                const float d = fmaf(m2x, tt.x,
                                fmaf(m2y, tt.y,
                                fmaf(m2z, tt.z, tt.w)));
                minAcc = fminf(minAcc, d);
            }
        }

        // overflow list (normally empty) — covers any slot >= CAP anywhere
        {
            const int no = min(g_ovf_cnt[sid_t], OVF_CAP);
            for (int k = 0; k < no; ++k) {
                const float4 tt = g_ovf[sid_t * OVF_CAP + k];
                const float d = fmaf(m2x, tt.x,
                                fmaf(m2y, tt.y,
                                fmaf(m2z, tt.z, tt.w)));
                minAcc = fminf(minAcc, d);
            }
        }

        // termination bound for the r=1 box
        const int x0 = max(cx - 1, 0), x1 = min(cx + 1, G - 1);
        const int y0 = max(cy - 1, 0), y1 = min(cy + 1, G - 1);
        const int z0 = max(cz - 1, 0), z1 = min(cz + 1, G - 1);
        float db = 3.4e38f;
        if (x0 > 0)     db = fminf(db, qx - (float)x0 * h);
        if (x1 < G - 1) db = fminf(db, (float)(x1 + 1) * h - qx);
        if (y0 > 0)     db = fminf(db, qy - (float)y0 * h);
        if (y1 < G - 1) db = fminf(db, (float)(y1 + 1) * h - qy);
        if (z0 > 0)     db = fminf(db, qz - (float)z0 * h);
        if (z1 < G - 1) db = fminf(db, (float)(z1 + 1) * h - qz);
        const bool full1 = (x0 == 0 && y0 == 0 && z0 == 0 &&
                            x1 == G - 1 && y1 == G - 1 && z1 == G - 1);

        if (!full1 && (qn + minAcc) > db * db) {
            // rare expansion: rescan full (2r+1)^3 box (in-cell slots only;
            // overflow already fully scanned above)
            int r = 2;
            while (true) {
                const int ex0 = max(cx - r, 0), ex1 = min(cx + r, G - 1);
                const int ey0 = max(cy - r, 0), ey1 = min(cy + r, G - 1);
                const int ez0 = max(cz - r, 0), ez1 = min(cz + r, G - 1);
                for (int z = ez0; z <= ez1; ++z)
                    for (int y = ey0; y <= ey1; ++y)
                        for (int x = ex0; x <= ex1; ++x) {
                            const int c  = (z * G + y) * G + x;
                            const int nc = min(cnt[c], CAP);
                            for (int k = 0; k < nc; ++k) {
                                const float4 tt = cell[c * CAP + k];
                                const float d = fmaf(m2x, tt.x,
                                                fmaf(m2y, tt.y,
                                                fmaf(m2z, tt.z, tt.w)));
                                minAcc = fminf(minAcc, d);
                            }
                        }
                float edb = 3.4e38f;
                if (ex0 > 0)     edb = fminf(edb, qx - (float)ex0 * h);
                if (ex1 < G - 1) edb = fminf(edb, (float)(ex1 + 1) * h - qx);
                if (ey0 > 0)     edb = fminf(edb, qy - (float)ey0 * h);
                if (ey1 < G - 1) edb = fminf(edb, (float)(ey1 + 1) * h - qy);
                if (ez0 > 0)     edb = fminf(edb, qz - (float)ez0 * h);
                if (ez1 < G - 1) edb = fminf(edb, (float)(ez1 + 1) * h - qz);
                const bool ef = (ex0 == 0 && ey0 == 0 && ez0 == 0 &&
                                 ex1 == G - 1 && ey1 == G - 1 && ez1 == G - 1);
                if (ef || (qn + minAcc) <= edb * edb) break;
                ++r;
            }
        }

        const float dist = fmaxf(qn + minAcc, 0.0f);
        if (dir == 0) accD0 += dist; else accD1 += dist;
    }

    // ---------------- Partials + last-CTA finalize ----------------
    {
        const float b0 = block_sum(accD0, redf);
        const float b1 = block_sum(accD1, redf);
        if (threadIdx.x == 0) {
            g_p0[blockIdx.x] = b0;
            g_p1[blockIdx.x] = b1;
            __threadfence();                               // release partials
            amLast = (atomicAdd(&g_done, 1u) == gridDim.x - 1);
        }
        __syncthreads();
    }

    if (amLast) {
        __threadfence();                                   // acquire partials
        float s0 = 0.f, s1 = 0.f;
        for (int i = threadIdx.x; i < (int)gridDim.x; i += BLK) {
            s0 += g_p0[i];
            s1 += g_p1[i];
        }
        const float t0 = block_sum(s0, redf);
        const float t1 = block_sum(s1, redf);

        // restore scratch state for the next graph replay
        {
            int4* cp = (int4*)g_cnt;
            const int n4 = (nsets * NC) >> 2;
            for (int i = threadIdx.x; i < n4; i += BLK)
                cp[i] = make_int4(0, 0, 0, 0);
            if (threadIdx.x < NSETS_MAX) g_ovf_cnt[threadIdx.x] = 0;
        }

        if (threadIdx.x == 0) {
            g_done = 0;
            const float rec = t0 / (float)((size_t)B * N) + t1 / (float)((size_t)B * M);
            for (int i = 0; i < out_size; ++i) out[i] = rec;   // (loss, rec_loss)
        }
    }
}

extern "C" void kernel_launch(void* const* d_in, const int* in_sizes, int n_in,
                              void* d_out, int out_size) {
    const float* pos  = (const float*)d_in[0];
    const float* xhat = (const float*)d_in[1];

    const int B = 2;
    const int N = in_sizes[0] / (B * 3);
    const int M = in_sizes[1] / (B * 3);

    int sms = 148;
    {
        int dev = 0;
        cudaGetDevice(&dev);
        int v = 0;
        if (cudaDeviceGetAttribute(&v, cudaDevAttrMultiProcessorCount, dev) == cudaSuccess && v > 0)
            sms = v;
    }
    int grid = 2 * sms;        // 2 CTAs/SM, wave-1 co-resident (barrier-safe)
    if (grid > MAXGRID) grid = MAXGRID;

    chamfer_onebar_kernel<<<grid, BLK>>>(pos, xhat, (float*)d_out, out_size, N, M, B);
}